// round 8
// baseline (speedup 1.0000x reference)
#include <cuda_runtime.h>

// ReactantCentreIdentify — fused segment-mean-gate-concat.
//   node_rep      [N=400000, D=300] f32
//   batch         [N] i32, SORTED ascending in [0, B=4096)
//   primary_label [N] i32 in {-1, 0}
//   out           [N, 600] f32 = [node_rep | cond_pool[batch]]
//
// TWO CTAs per graph (grid=8192): bid = 2g+half. Each half-CTA streams its
// contiguous half of the graph's rows (pass 1: copy left, accumulate cond
// rows in registers with column ownership), publishes a partial sum/count to
// device scratch, and the second-arriving CTA of the pair computes the gated
// pooled mean; the first spins on a flag (it arrives only after its own heavy
// pass-1, partner is the adjacent bid => co-resident; >=303 full pairs always
// resident => progress guaranteed). Both CTAs then write the pool into the
// right half of their rows. Halved per-CTA quantum => halved end-of-kernel
// drain, the dominant remaining loss. Sync flags self-reset for graph replay.

#define D4   75          // D/4 float4 per input row
#define OUT4 150         // 2D/4 float4 per output row
#define BY   6           // row lanes per block
#define PFR  12          // prefetch distance in rows
#define NGRAPH 4096
#define SWIN 2048        // binary-search half-window (6.5 sigma; has fallback)

__device__ float4       g_part[2 * NGRAPH][D4];  // per half-CTA partial sums
__device__ int          g_cntp[2 * NGRAPH];
__device__ float4       g_pool[NGRAPH][D4];
__device__ unsigned int g_ready[NGRAPH];         // arrival tickets (self-reset)
__device__ unsigned int g_pflag[NGRAPH];         // pool-published flag
__device__ unsigned int g_done[NGRAPH];          // completion count (self-reset)

__global__ __launch_bounds__(D4 * BY, 4)
void reactant_centre_kernel(const float4* __restrict__ x4,     // [N, 75]
                            const int*    __restrict__ batch,  // [N]
                            const int*    __restrict__ label,  // [N]
                            float4*       __restrict__ out4,   // [N, 150]
                            int n)
{
    const int bid  = blockIdx.x;
    const int g    = bid >> 1;
    const int half = bid & 1;
    const int c4   = threadIdx.x;   // 0..74  (float4 column)
    const int ry   = threadIdx.y;   // 0..BY-1 (row lane)
    const int tid  = ry * D4 + c4;

    __shared__ int    s_se[2];
    __shared__ float4 s_acc[BY][D4];
    __shared__ int    s_cnt[BY];
    __shared__ float4 s_pool[D4];
    __shared__ int    s_ticket;

    // lower_bound for g and g+1, windowed around the expected position.
    if (tid < 2) {
        int target = g + tid;
        long est = ((long)target * n) / NGRAPH;
        int lo = (int)(est - SWIN); if (lo < 0) lo = 0;
        int hi = (int)(est + SWIN); if (hi > n) hi = n;
        // correctness fallback if the window assumption ever fails
        if (lo > 0 && batch[lo] >= target) lo = 0;
        if (hi < n && batch[hi - 1] < target) hi = n;
        while (lo < hi) {
            int mid = (lo + hi) >> 1;
            if (batch[mid] < target) lo = mid + 1; else hi = mid;
        }
        s_se[tid] = lo;
    }
    __syncthreads();
    const int s   = s_se[0];
    const int e   = s_se[1];
    const int mid = (s + e) >> 1;
    const int rs  = half ? mid : s;
    const int re  = half ? e   : mid;

    const bool do_pf = ((c4 & 7) == 0);   // one prefetcher per 128B line
    const int  pmax  = n - 1;

    // ---- Pass 1: copy left half + accumulate condition rows (my half) ----
    float4 acc = make_float4(0.f, 0.f, 0.f, 0.f);
    int cnt = 0;
    for (int r = rs + ry; r < re; r += BY) {
        if (do_pf) {
            int rp = r + PFR;                 // may run into the next graph:
            if (rp > pmax) rp = pmax;         // harmless, even helpful
            asm volatile("prefetch.global.L2 [%0];"
                         :: "l"(x4 + (long)rp * D4 + c4));
        }
        float4 v = x4[(long)r * D4 + c4];
        int   l = label[r];
        out4[(long)r * OUT4 + c4] = v;
        if (l == -1) {
            acc.x += v.x; acc.y += v.y; acc.z += v.z; acc.w += v.w;
            cnt++;
        }
    }
    s_acc[ry][c4] = acc;
    if (c4 == 0) s_cnt[ry] = cnt;
    __syncthreads();

    // Publish this half-CTA's partial.
    if (ry == 0) {
        float4 t = s_acc[0][c4];
        int tc_i = s_cnt[0];
        #pragma unroll
        for (int k = 1; k < BY; k++) {
            float4 a = s_acc[k][c4];
            t.x += a.x; t.y += a.y; t.z += a.z; t.w += a.w;
            tc_i += s_cnt[k];
        }
        g_part[bid][c4] = t;
        if (c4 == 0) g_cntp[bid] = tc_i;
    }
    __syncthreads();

    if (tid == 0) {
        __threadfence();                              // release partials
        s_ticket = (int)atomicAdd(&g_ready[g], 1u);   // arrival ticket
    }
    __syncthreads();

    if (s_ticket == 1) {
        // Second arrival: partner's partial is published. Compute pool.
        __threadfence();                              // acquire partials
        if (ry == 0) {
            float4 a = g_part[2 * g][c4];
            float4 b = g_part[2 * g + 1][c4];
            int   tc = g_cntp[2 * g] + g_cntp[2 * g + 1];
            bool flag = (e > s) && (label[e - 1] == -1);
            float inv = flag ? (1.0f / fmaxf((float)tc, 1.0f)) : 0.0f;
            float4 p = make_float4((a.x + b.x) * inv, (a.y + b.y) * inv,
                                   (a.z + b.z) * inv, (a.w + b.w) * inv);
            g_pool[g][c4] = p;
            s_pool[c4]    = p;
        }
        __syncthreads();
        if (tid == 0) { __threadfence(); atomicExch(&g_pflag[g], 1u); }
    } else {
        // First arrival: wait for the pool (partner is the adjacent bid).
        if (tid == 0) {
            while (atomicAdd(&g_pflag[g], 0u) == 0u) __nanosleep(64);
        }
        __syncthreads();
        __threadfence();                              // acquire pool
        if (ry == 0) s_pool[c4] = g_pool[g][c4];
        __syncthreads();
    }

    // ---- Pass 2: broadcast pooled vector into right half (my rows) ----
    const float4 p = s_pool[c4];
    for (int r = rs + ry; r < re; r += BY) {
        out4[(long)r * OUT4 + D4 + c4] = p;
    }

    // Self-reset sync state so graph replays start clean (deterministic:
    // last CTA of the pair clears; all output writes precede the fence).
    __syncthreads();
    if (tid == 0) {
        __threadfence();
        if (atomicAdd(&g_done[g], 1u) == 1u) {
            g_ready[g] = 0;
            g_pflag[g] = 0;
            g_done[g]  = 0;
            __threadfence();
        }
    }
}

extern "C" void kernel_launch(void* const* d_in, const int* in_sizes, int n_in,
                              void* d_out, int out_size)
{
    const float* node_rep = (const float*)d_in[0];
    const int*   batch    = (const int*)d_in[1];
    const int*   label    = (const int*)d_in[2];
    (void)n_in; (void)out_size;

    const int n = in_sizes[1];        // N from batch array

    dim3 block(D4, BY);               // 75 x 6 = 450 threads
    reactant_centre_kernel<<<2 * NGRAPH, block>>>((const float4*)node_rep,
                                                  batch, label,
                                                  (float4*)d_out, n);
}

// round 9
// speedup vs baseline: 1.3889x; 1.3889x over previous
#include <cuda_runtime.h>

// ReactantCentreIdentify — fused segment-mean-gate-concat.
//   node_rep      [N=400000, D=300] f32
//   batch         [N] i32, SORTED ascending in [0, B=4096)
//   primary_label [N] i32 in {-1, 0}
//   out           [N, 600] f32 = [node_rep | cond_pool[batch]]
//
// One CTA per graph (grid=4096), block (75,6)=450 threads, 4 CTAs/SM
// (the proven 60-warp bandwidth config). Read-twice / write-once-dense:
//   Loop 1: read labels + CONDITION rows only (~half the rows), accumulate
//           per-column partial sums in registers. No stores.
//   Reduce + gate (last-node label) + 1/max(cnt,1) -> pooled vector.
//   Loop 2: re-read every row (condition rows hit L2 — the gap between a
//           CTA's loop1 and loop2 is only a few us) and write the FULL
//           2400B output row contiguously: [row | pool].
// vs the two-half-stream scheme this doubles DRAM write page locality and
// eliminates the 16B sector straddle at byte 1200 of every row (400K
// partial-sector RMWs). L2 prefetch ~12 rows ahead in both loops; loop 1
// prefetches only rows whose label-ahead says condition.

#define D4   75          // D/4 float4 per input row
#define OUT4 150         // 2D/4 float4 per output row
#define BY   6           // row lanes per block
#define PFR  12          // prefetch distance in rows
#define NGRAPH 4096
#define SWIN 2048        // binary-search half-window (6.5 sigma; has fallback)

__global__ __launch_bounds__(D4 * BY, 4)
void reactant_centre_kernel(const float4* __restrict__ x4,     // [N, 75]
                            const int*    __restrict__ batch,  // [N]
                            const int*    __restrict__ label,  // [N]
                            float4*       __restrict__ out4,   // [N, 150]
                            int n)
{
    const int g   = blockIdx.x;
    const int c4  = threadIdx.x;   // 0..74  (float4 column)
    const int ry  = threadIdx.y;   // 0..BY-1 (row lane)
    const int tid = ry * D4 + c4;

    __shared__ int    s_se[2];
    __shared__ float4 s_acc[BY][D4];
    __shared__ int    s_cnt[BY];
    __shared__ float4 s_pool[D4];

    // lower_bound for g and g+1, windowed around the expected position.
    if (tid < 2) {
        int target = g + tid;
        long est = ((long)target * n) / NGRAPH;
        int lo = (int)(est - SWIN); if (lo < 0) lo = 0;
        int hi = (int)(est + SWIN); if (hi > n) hi = n;
        // correctness fallback if the window assumption ever fails
        if (lo > 0 && batch[lo] >= target) lo = 0;
        if (hi < n && batch[hi - 1] < target) hi = n;
        while (lo < hi) {
            int mid = (lo + hi) >> 1;
            if (batch[mid] < target) lo = mid + 1; else hi = mid;
        }
        s_se[tid] = lo;
    }
    __syncthreads();
    const int s = s_se[0];
    const int e = s_se[1];

    const bool do_pf = ((c4 & 7) == 0);   // one prefetcher per 128B line
    const int  pmax  = n - 1;

    // ---- Loop 1: accumulate condition rows only (no stores) ----
    float4 acc = make_float4(0.f, 0.f, 0.f, 0.f);
    int cnt = 0;
    for (int r = s + ry; r < e; r += BY) {
        if (do_pf) {
            int rp = r + PFR;
            if (rp > pmax) rp = pmax;
            if (label[rp] == -1) {           // only warm rows we'll load here
                asm volatile("prefetch.global.L2 [%0];"
                             :: "l"(x4 + (long)rp * D4 + c4));
            }
        }
        if (label[r] == -1) {
            float4 v = x4[(long)r * D4 + c4];
            acc.x += v.x; acc.y += v.y; acc.z += v.z; acc.w += v.w;
            cnt++;
        }
    }
    s_acc[ry][c4] = acc;
    if (c4 == 0) s_cnt[ry] = cnt;
    __syncthreads();

    // Gate: pool only if the LAST node of the graph is a condition node.
    const bool flag = (e > s) && (label[e - 1] == -1);

    if (ry == 0) {
        float4 t = s_acc[0][c4];
        int tc_i = s_cnt[0];
        #pragma unroll
        for (int k = 1; k < BY; k++) {
            float4 a = s_acc[k][c4];
            t.x += a.x; t.y += a.y; t.z += a.z; t.w += a.w;
            tc_i += s_cnt[k];
        }
        float inv = flag ? (1.0f / fmaxf((float)tc_i, 1.0f)) : 0.0f;
        s_pool[c4] = make_float4(t.x * inv, t.y * inv, t.z * inv, t.w * inv);
    }
    __syncthreads();

    // ---- Loop 2: re-read rows (cond rows hit L2) and write FULL dense row ----
    const float4 p = s_pool[c4];
    for (int r = s + ry; r < e; r += BY) {
        if (do_pf) {
            int rp = r + PFR;
            if (rp > pmax) rp = pmax;
            asm volatile("prefetch.global.L2 [%0];"
                         :: "l"(x4 + (long)rp * D4 + c4));
        }
        float4 v = x4[(long)r * D4 + c4];
        out4[(long)r * OUT4 + c4]      = v;   // left half
        out4[(long)r * OUT4 + D4 + c4] = p;   // right half — same row, dense
    }
}

extern "C" void kernel_launch(void* const* d_in, const int* in_sizes, int n_in,
                              void* d_out, int out_size)
{
    const float* node_rep = (const float*)d_in[0];
    const int*   batch    = (const int*)d_in[1];
    const int*   label    = (const int*)d_in[2];
    (void)n_in; (void)out_size;

    const int n = in_sizes[1];        // N from batch array

    dim3 block(D4, BY);               // 75 x 6 = 450 threads
    reactant_centre_kernel<<<NGRAPH, block>>>((const float4*)node_rep, batch,
                                              label, (float4*)d_out, n);
}

// round 10
// speedup vs baseline: 1.4846x; 1.0689x over previous
#include <cuda_runtime.h>

// ReactantCentreIdentify — fused segment-mean-gate-concat.
//   node_rep      [N=400000, D=300] f32
//   batch         [N] i32, SORTED ascending in [0, B=4096)
//   primary_label [N] i32 in {-1, 0}
//   out           [N, 600] f32 = [node_rep | cond_pool[batch]]
//
// TWO CTAs per graph, split by COLUMNS (sync-free): bid=2g+half.
//   half 0 owns float4 cols [0,38), half 1 owns [38,75).
// The pooled mean of a column subset needs only that subset's values over all
// rows plus the condition count (from labels, read by both halves, L2-shared)
// => each CTA computes its pool columns completely locally. Same total DRAM
// traffic as the 1-CTA/graph kernel (row segments are sector-exact), but the
// per-CTA quantum halves (34us -> 17us), shrinking the end-of-kernel drain —
// the dominant residual loss (R7 validated: quantum down 18us -> time down
// 10us). Block (38,12)=456 thr = 15 warps, 4 CTAs/SM -> 60 warps/SM (the
// proven bandwidth engine). Windowed binary search; L2 prefetch 12 rows ahead.

#define D4   75          // D/4 float4 per input row
#define OUT4 150         // 2D/4 float4 per output row
#define XW   38          // block x dim (max cols per half)
#define BY   12          // row lanes per block
#define PFR  12          // prefetch distance in rows
#define NGRAPH 4096
#define SWIN 2048        // binary-search half-window (6.5 sigma; has fallback)

__global__ __launch_bounds__(XW * BY, 4)
void reactant_centre_kernel(const float4* __restrict__ x4,     // [N, 75]
                            const int*    __restrict__ batch,  // [N]
                            const int*    __restrict__ label,  // [N]
                            float4*       __restrict__ out4,   // [N, 150]
                            int n)
{
    const int bid  = blockIdx.x;
    const int g    = bid >> 1;
    const int half = bid & 1;
    const int cx   = threadIdx.x;            // 0..37 (local col)
    const int ry   = threadIdx.y;            // 0..11 (row lane)
    const int tid  = ry * XW + cx;

    const int  cw  = half ? (D4 - XW) : XW;  // 37 or 38 active cols
    const int  c4  = (half ? XW : 0) + cx;   // global float4 col
    const bool act = cx < cw;

    __shared__ int    s_se[2];
    __shared__ float4 s_acc[BY][XW];
    __shared__ int    s_cnt[BY];
    __shared__ float4 s_pool[XW];

    // lower_bound for g and g+1, windowed around the expected position.
    if (tid < 2) {
        int target = g + tid;
        long est = ((long)target * n) / NGRAPH;
        int lo = (int)(est - SWIN); if (lo < 0) lo = 0;
        int hi = (int)(est + SWIN); if (hi > n) hi = n;
        // correctness fallback if the window assumption ever fails
        if (lo > 0 && batch[lo] >= target) lo = 0;
        if (hi < n && batch[hi - 1] < target) hi = n;
        while (lo < hi) {
            int mid = (lo + hi) >> 1;
            if (batch[mid] < target) lo = mid + 1; else hi = mid;
        }
        s_se[tid] = lo;
    }
    __syncthreads();
    const int s = s_se[0];
    const int e = s_se[1];

    const bool do_pf = act && ((cx & 7) == 0);   // one prefetcher per 128B line
    const int  pmax  = n - 1;

    // ---- Pass 1: copy my left-half columns + accumulate condition rows ----
    float4 acc = make_float4(0.f, 0.f, 0.f, 0.f);
    int cnt = 0;
    for (int r = s + ry; r < e; r += BY) {
        if (do_pf) {
            int rp = r + PFR;                 // may cross into next graph:
            if (rp > pmax) rp = pmax;         // harmless pre-warming
            asm volatile("prefetch.global.L2 [%0];"
                         :: "l"(x4 + (long)rp * D4 + c4));
        }
        if (act) {
            float4 v = x4[(long)r * D4 + c4];
            int   l = label[r];
            out4[(long)r * OUT4 + c4] = v;
            if (l == -1) {
                acc.x += v.x; acc.y += v.y; acc.z += v.z; acc.w += v.w;
                cnt++;
            }
        }
    }
    s_acc[ry][cx] = acc;
    if (cx == 0) s_cnt[ry] = cnt;
    __syncthreads();

    // Gate: pool only if the LAST node of the graph is a condition node.
    const bool flag = (e > s) && (label[e - 1] == -1);

    if (ry == 0) {
        float4 t = s_acc[0][cx];
        int tc_i = s_cnt[0];
        #pragma unroll
        for (int k = 1; k < BY; k++) {
            float4 a = s_acc[k][cx];
            t.x += a.x; t.y += a.y; t.z += a.z; t.w += a.w;
            tc_i += s_cnt[k];
        }
        float inv = flag ? (1.0f / fmaxf((float)tc_i, 1.0f)) : 0.0f;
        s_pool[cx] = make_float4(t.x * inv, t.y * inv, t.z * inv, t.w * inv);
    }
    __syncthreads();

    // ---- Pass 2: broadcast my pool columns into the right half ----
    const float4 p = s_pool[cx];
    for (int r = s + ry; r < e; r += BY) {
        if (act) out4[(long)r * OUT4 + D4 + c4] = p;
    }
}

extern "C" void kernel_launch(void* const* d_in, const int* in_sizes, int n_in,
                              void* d_out, int out_size)
{
    const float* node_rep = (const float*)d_in[0];
    const int*   batch    = (const int*)d_in[1];
    const int*   label    = (const int*)d_in[2];
    (void)n_in; (void)out_size;

    const int n = in_sizes[1];        // N from batch array

    dim3 block(XW, BY);               // 38 x 12 = 456 threads
    reactant_centre_kernel<<<2 * NGRAPH, block>>>((const float4*)node_rep,
                                                  batch, label,
                                                  (float4*)d_out, n);
}